// round 16
// baseline (speedup 1.0000x reference)
#include <cuda_runtime.h>
#include <cstdint>
#include <math.h>

#define SEQ 2048
#define HID 2048
#define NH  16
#define NKV 4
#define HD  128
#define KVD (NKV*HD)   // 512
#define NQKV (HID + 2*KVD)   // 3072

// Scratch (no cudaMalloc allowed)
__device__ float g_q[SEQ*HID];
__device__ float g_k[SEQ*KVD];
__device__ float g_v[SEQ*KVD];
__device__ float g_o[SEQ*HID];
__device__ float g_xr[SEQ*HID];        // tf32-rounded x
__device__ float g_wqkv[NQKV*HID];     // tf32-rounded [wq;wk;wv]
__device__ float g_wor[HID*HID];       // tf32-rounded wo

// fp32 -> tf32 round-to-nearest
__device__ __forceinline__ float f32_to_tf32(float x) {
    uint32_t y;
    asm("cvt.rna.tf32.f32 %0, %1;" : "=r"(y) : "f"(x));
    return __uint_as_float(y);
}

__device__ __forceinline__ void mma_tf32_16x8x8(
    float c[4], uint32_t a0, uint32_t a1, uint32_t a2, uint32_t a3,
    uint32_t b0, uint32_t b1)
{
    asm volatile(
        "mma.sync.aligned.m16n8k8.row.col.f32.tf32.tf32.f32 "
        "{%0,%1,%2,%3}, {%4,%5,%6,%7}, {%8,%9}, {%0,%1,%2,%3};"
        : "+f"(c[0]), "+f"(c[1]), "+f"(c[2]), "+f"(c[3])
        : "r"(a0), "r"(a1), "r"(a2), "r"(a3), "r"(b0), "r"(b1));
}

__device__ __forceinline__ void ldsm4(
    uint32_t& d0, uint32_t& d1, uint32_t& d2, uint32_t& d3, uint32_t addr)
{
    asm volatile("ldmatrix.sync.aligned.m8n8.x4.shared.b16 {%0,%1,%2,%3}, [%4];"
                 : "=r"(d0), "=r"(d1), "=r"(d2), "=r"(d3) : "r"(addr));
}

__device__ __forceinline__ uint32_t smem_to_u32(const void* p) {
    uint32_t a;
    asm("{ .reg .u64 t; cvta.to.shared.u64 t, %1; cvt.u32.u64 %0, t; }"
        : "=r"(a) : "l"(p));
    return a;
}

__device__ __forceinline__ void cp16(uint32_t dst, const void* src) {
    asm volatile("cp.async.cg.shared.global [%0], [%1], 16;" :: "r"(dst), "l"(src));
}
#define CP_COMMIT() asm volatile("cp.async.commit_group;")
#define CP_WAIT1()  asm volatile("cp.async.wait_group 1;")
#define CP_WAIT0()  asm volatile("cp.async.wait_group 0;")

// ============================================================================
// tf32 mma.sync GEMM mainloop (2-stage cp.async, ldmatrix frag loads)
// CTA 128x128, BK=32, 256 threads, warp grid 4m x 2n (warp tile 32x64)
// ============================================================================
#define BK 32
#define AST 36
#define ABUF (128*AST)
#define GEMM_SMEM (2*2*ABUF*4)           // 73728 bytes

__device__ __forceinline__ void gemm_mainloop(
    const float* __restrict__ A, const float* __restrict__ B,
    int row0, int col0, float* sm, float c[2][8][4])
{
    const int tid  = threadIdx.x;
    const int lane = tid & 31;
    const int wid  = tid >> 5;
    const int wm0  = (wid & 3) * 32;
    const int wn0  = (wid >> 2) * 64;
    const int lr   = tid >> 3;
    const int lc   = (tid & 7) * 4;

    const uint32_t smb = smem_to_u32(sm);

    const int mi = lane >> 3, r8 = lane & 7;
    const uint32_t a_off0 = (uint32_t)((wm0 +      (mi & 1)*8 + r8)*AST + (mi >> 1)*4) * 4;
    const uint32_t a_off1 = a_off0 + 16u*AST*4;
    uint32_t b_off[4];
    #pragma unroll
    for (int jp = 0; jp < 4; ++jp)
        b_off[jp] = (uint32_t)((wn0 + 16*jp + (mi >> 1)*8 + r8)*AST + (mi & 1)*4) * 4
                    + (uint32_t)ABUF*4;

    #pragma unroll
    for (int i = 0; i < 2; ++i)
        #pragma unroll
        for (int j = 0; j < 8; ++j)
            #pragma unroll
            for (int t = 0; t < 4; ++t) c[i][j][t] = 0.f;

    // prologue: stage kb=0 into buf 0
    #pragma unroll
    for (int it = 0; it < 4; ++it) {
        const int r = lr + it * 32;
        cp16(smb + (uint32_t)(r*AST + lc)*4,          A + (size_t)(row0 + r)*HID + lc);
        cp16(smb + (uint32_t)(ABUF + r*AST + lc)*4,   B + (size_t)(col0 + r)*HID + lc);
    }
    CP_COMMIT();

    const int NKB = HID / BK;   // 64
    for (int kb = 0; kb < NKB; ++kb) {
        const int cur = kb & 1;
        if (kb + 1 < NKB) {
            const int nxt = 1 - cur;
            const int k0g = (kb + 1) * BK;
            #pragma unroll
            for (int it = 0; it < 4; ++it) {
                const int r = lr + it * 32;
                cp16(smb + (uint32_t)(nxt*2*ABUF + r*AST + lc)*4,
                     A + (size_t)(row0 + r)*HID + k0g + lc);
                cp16(smb + (uint32_t)(nxt*2*ABUF + ABUF + r*AST + lc)*4,
                     B + (size_t)(col0 + r)*HID + k0g + lc);
            }
            CP_COMMIT();
            CP_WAIT1();
        } else {
            CP_WAIT0();
        }
        __syncthreads();

        const uint32_t bufb = smb + (uint32_t)(cur * 2 * ABUF) * 4;
        #pragma unroll
        for (int s = 0; s < 4; ++s) {
            const uint32_t soff = (uint32_t)s * 32;
            uint32_t af[2][4], bf[8][2];
            ldsm4(af[0][0], af[0][1], af[0][2], af[0][3], bufb + a_off0 + soff);
            ldsm4(af[1][0], af[1][1], af[1][2], af[1][3], bufb + a_off1 + soff);
            #pragma unroll
            for (int jp = 0; jp < 4; ++jp)
                ldsm4(bf[2*jp][0], bf[2*jp][1], bf[2*jp+1][0], bf[2*jp+1][1],
                      bufb + b_off[jp] + soff);
            #pragma unroll
            for (int i = 0; i < 2; ++i)
                #pragma unroll
                for (int j = 0; j < 8; ++j)
                    mma_tf32_16x8x8(c[i][j], af[i][0], af[i][1], af[i][2], af[i][3],
                                    bf[j][0], bf[j][1]);
        }
        __syncthreads();
    }
}

// Persistent fused QKV projection: C[2048, 3072] = xr @ Wqkv^T, routed.
#define QKV_TX (NQKV/128)      // 24
#define QKV_NT (QKV_TX * (SEQ/128))   // 384 tiles
__global__ __launch_bounds__(256, 2) void gemm_qkv(
    const float* __restrict__ A, const float* __restrict__ B,
    float* __restrict__ Cq, float* __restrict__ Ck, float* __restrict__ Cv)
{
    extern __shared__ float sm[];
    const int lane = threadIdx.x & 31;
    const int wid  = threadIdx.x >> 5;
    const int wm0  = (wid & 3) * 32;
    const int wn0  = (wid >> 2) * 64;
    const int gr   = lane >> 2;
    const int gk   = lane & 3;

    for (int tidx = blockIdx.x; tidx < QKV_NT; tidx += gridDim.x) {
        const int row0 = (tidx / QKV_TX) * 128;
        const int col0 = (tidx % QKV_TX) * 128;

        float c[2][8][4];
        gemm_mainloop(A, B, row0, col0, sm, c);

        float* Cd; int ldc, cb;
        if (col0 < HID)            { Cd = Cq; ldc = HID; cb = col0; }
        else if (col0 < HID + KVD) { Cd = Ck; ldc = KVD; cb = col0 - HID; }
        else                       { Cd = Cv; ldc = KVD; cb = col0 - HID - KVD; }

        #pragma unroll
        for (int i = 0; i < 2; ++i) {
            #pragma unroll
            for (int j = 0; j < 8; ++j) {
                const int colb = cb + wn0 + j*8 + gk*2;
                const int rowa = row0 + wm0 + i*16 + gr;
                *(float2*)&Cd[(size_t)rowa * ldc + colb]       = make_float2(c[i][j][0], c[i][j][1]);
                *(float2*)&Cd[(size_t)(rowa + 8) * ldc + colb] = make_float2(c[i][j][2], c[i][j][3]);
            }
        }
    }
}

// Plain GEMM (O projection): C[2048, 2048] = A @ B^T (256 tiles, 1 wave)
__global__ __launch_bounds__(256, 2) void gemm_o(
    const float* __restrict__ A, const float* __restrict__ B,
    float* __restrict__ C)
{
    extern __shared__ float sm[];
    const int row0 = blockIdx.y * 128;
    const int col0 = blockIdx.x * 128;

    float c[2][8][4];
    gemm_mainloop(A, B, row0, col0, sm, c);

    const int lane = threadIdx.x & 31;
    const int wid  = threadIdx.x >> 5;
    const int wm0  = (wid & 3) * 32;
    const int wn0  = (wid >> 2) * 64;
    const int gr   = lane >> 2;
    const int gk   = lane & 3;

    #pragma unroll
    for (int i = 0; i < 2; ++i) {
        #pragma unroll
        for (int j = 0; j < 8; ++j) {
            const int colb = col0 + wn0 + j*8 + gk*2;
            const int rowa = row0 + wm0 + i*16 + gr;
            *(float2*)&C[(size_t)rowa * HID + colb]       = make_float2(c[i][j][0], c[i][j][1]);
            *(float2*)&C[(size_t)(rowa + 8) * HID + colb] = make_float2(c[i][j][2], c[i][j][3]);
        }
    }
}

// ---------------------------------------------------------------------------
// Fused elementwise tf32 rounding: x, wq|wk|wv -> wqkv, wo  (one launch)
// ---------------------------------------------------------------------------
#define N4_X   (SEQ*HID/4)
#define N4_WQ  (HID*HID/4)
#define N4_WK  (KVD*HID/4)
#define N4_WV  (KVD*HID/4)
#define N4_WO  (HID*HID/4)
#define N4_TOT (N4_X + N4_WQ + N4_WK + N4_WV + N4_WO)

__global__ void roundcvt_all(
    const float4* __restrict__ x,  const float4* __restrict__ wq,
    const float4* __restrict__ wk, const float4* __restrict__ wv,
    const float4* __restrict__ wo,
    float4* __restrict__ xr, float4* __restrict__ wqkv, float4* __restrict__ wor)
{
    for (int i = blockIdx.x * blockDim.x + threadIdx.x; i < N4_TOT;
         i += gridDim.x * blockDim.x) {
        const float4* s; float4* d; int off = i;
        if (off < N4_X)                    { s = x;  d = xr; }
        else if ((off -= N4_X)  < N4_WQ)   { s = wq; d = wqkv; }
        else if ((off -= N4_WQ) < N4_WK)   { s = wk; d = wqkv + N4_WQ; }
        else if ((off -= N4_WK) < N4_WV)   { s = wv; d = wqkv + N4_WQ + N4_WK; }
        else                               { off -= N4_WV; s = wo; d = wor; }
        float4 v = s[off];
        d[off] = make_float4(f32_to_tf32(v.x), f32_to_tf32(v.y),
                             f32_to_tf32(v.z), f32_to_tf32(v.w));
    }
}

// ---------------------------------------------------------------------------
// RoPE (interleaved-pair variant), in place.
// ---------------------------------------------------------------------------
__global__ void rope_kernel(float* __restrict__ data,
                            const float* __restrict__ cosv,
                            const float* __restrict__ sinv,
                            int nheads)
{
    int idx = blockIdx.x * blockDim.x + threadIdx.x;
    int total = SEQ * nheads * 32;
    if (idx >= total) return;
    int i   = idx & 31;
    int rem = idx >> 5;
    int h   = rem % nheads;
    int s   = rem / nheads;

    float* p = data + ((size_t)s * nheads + h) * HD;
    int j0 = 2*i, j1 = 2*i + 1;

    float x0  = p[j0],     x1  = p[j1];
    float xp0 = p[64+j0],  xp1 = p[64+j1];
    float c0 = cosv[s*HD + j0], s0 = sinv[s*HD + j0];
    float c1 = cosv[s*HD + j1], s1 = sinv[s*HD + j1];

    float r0 = -x1;
    float r1 =  x0;

    p[j0]     =  r0*c0 + xp0*s0;
    p[j1]     =  r1*c1 + xp1*s1;
    p[64+j0]  = -r0*s0 + xp0*c0;
    p[64+j1]  = -r1*s1 + xp1*c1;
}

// ============================================================================
// Tensor-core causal flash attention (tf32 mma.sync), GQA.
// BM=128 (8 warps x m16), BN=64, HD=128. Q frags in registers; 1 CTA/SM.
// smem: K[64][132] | V[64][132] | per-warp P[16][68] x8
// ============================================================================
#define KST 132
#define PST 68
#define FL_KV   (64*KST)
#define FL_PBUF (16*PST)
#define FL_SMEM ((2*FL_KV + 8*FL_PBUF) * 4)       // 102400 bytes

__global__ __launch_bounds__(256, 1) void flash_mma(
    const float* __restrict__ q_g, const float* __restrict__ k_g,
    const float* __restrict__ v_g, float* __restrict__ o_g)
{
    extern __shared__ float sm[];
    float* Ks = sm;
    float* Vs = sm + FL_KV;

    const int tid  = threadIdx.x;
    const int lane = tid & 31;
    const int wid  = tid >> 5;          // 0..7
    const int gr   = lane >> 2;
    const int gk   = lane & 3;

    float* Pw = sm + 2*FL_KV + wid * FL_PBUF;

    const int qb    = gridDim.x - 1 - blockIdx.x;   // big-work CTAs first
    const int head  = blockIdx.y;
    const int kvh   = head >> 2;
    const int qrow0 = qb * 128;
    const int wrow  = qrow0 + wid * 16;
    const float scale = 0.08838834764831845f;

    // Q a-fragments in registers (loop-invariant across jb).
    uint32_t qa[16][4];
    {
        const float* qr0 = q_g + (size_t)(wrow + gr)     * HID + head*HD;
        const float* qr1 = q_g + (size_t)(wrow + gr + 8) * HID + head*HD;
        #pragma unroll
        for (int t = 0; t < 16; ++t) {
            const int k0 = t * 8;
            qa[t][0] = __float_as_uint(f32_to_tf32(qr0[k0 + gk]     * scale));
            qa[t][1] = __float_as_uint(f32_to_tf32(qr1[k0 + gk]     * scale));
            qa[t][2] = __float_as_uint(f32_to_tf32(qr0[k0 + gk + 4] * scale));
            qa[t][3] = __float_as_uint(f32_to_tf32(qr1[k0 + gk + 4] * scale));
        }
    }

    float o[16][4];
    #pragma unroll
    for (int j = 0; j < 16; ++j)
        #pragma unroll
        for (int t = 0; t < 4; ++t) o[j][t] = 0.f;
    float m0 = -1e30f, m1 = -1e30f, l0 = 0.f, l1 = 0.f;

    const int njb = 2*qb + 2;           // KV tiles of 64 covering 128 q-rows
    for (int jb = 0; jb < njb; ++jb) {
        const int kr0 = jb * 64;
        __syncthreads();
        // Load K and V tiles (64 rows x 128): 8 warps, 8 rows each per it
        #pragma unroll
        for (int it = 0; it < 8; ++it) {
            const int r = wid + 8*it;
            float4 kv = *(const float4*)(k_g + (size_t)(kr0 + r)*KVD + kvh*HD + 4*lane);
            float4 kt = make_float4(f32_to_tf32(kv.x), f32_to_tf32(kv.y),
                                    f32_to_tf32(kv.z), f32_to_tf32(kv.w));
            *(float4*)&Ks[r*KST + 4*lane] = kt;
            float4 vv = *(const float4*)(v_g + (size_t)(kr0 + r)*KVD + kvh*HD + 4*lane);
            float4 vt = make_float4(f32_to_tf32(vv.x), f32_to_tf32(vv.y),
                                    f32_to_tf32(vv.z), f32_to_tf32(vv.w));
            *(float4*)&Vs[r*KST + 4*lane] = vt;
        }
        __syncthreads();

        // S = Q K^T  (per warp: m16 x n64, K=128)
        float s[8][4];
        #pragma unroll
        for (int j = 0; j < 8; ++j)
            #pragma unroll
            for (int t = 0; t < 4; ++t) s[j][t] = 0.f;

        #pragma unroll
        for (int t = 0; t < 16; ++t) {
            const int k0 = t * 8;
            #pragma unroll
            for (int j = 0; j < 8; ++j) {
                const int base = (8*j + gr)*KST + k0 + gk;
                mma_tf32_16x8x8(s[j], qa[t][0], qa[t][1], qa[t][2], qa[t][3],
                                __float_as_uint(Ks[base]),
                                __float_as_uint(Ks[base + 4]));
            }
        }

        // Causal mask (tiles overlapping/above this warp's rows)
        if (kr0 + 63 > wrow) {
            const int r0 = wrow + gr, r1 = r0 + 8;
            #pragma unroll
            for (int j = 0; j < 8; ++j) {
                const int col = kr0 + 8*j + 2*gk;
                if (col     > r0) s[j][0] = -1e30f;
                if (col + 1 > r0) s[j][1] = -1e30f;
                if (col     > r1) s[j][2] = -1e30f;
                if (col + 1 > r1) s[j][3] = -1e30f;
            }
        }

        // Online softmax (rows gr and gr+8; stats spread over quad lanes)
        float rmax0 = -1e30f, rmax1 = -1e30f;
        #pragma unroll
        for (int j = 0; j < 8; ++j) {
            rmax0 = fmaxf(rmax0, fmaxf(s[j][0], s[j][1]));
            rmax1 = fmaxf(rmax1, fmaxf(s[j][2], s[j][3]));
        }
        rmax0 = fmaxf(rmax0, __shfl_xor_sync(0xffffffffu, rmax0, 1));
        rmax0 = fmaxf(rmax0, __shfl_xor_sync(0xffffffffu, rmax0, 2));
        rmax1 = fmaxf(rmax1, __shfl_xor_sync(0xffffffffu, rmax1, 1));
        rmax1 = fmaxf(rmax1, __shfl_xor_sync(0xffffffffu, rmax1, 2));

        const float m0n = fmaxf(m0, rmax0);
        const float m1n = fmaxf(m1, rmax1);
        const float f0  = __expf(m0 - m0n);
        const float f1  = __expf(m1 - m1n);

        float sum0 = 0.f, sum1 = 0.f;
        #pragma unroll
        for (int j = 0; j < 8; ++j) {
            s[j][0] = __expf(s[j][0] - m0n);
            s[j][1] = __expf(s[j][1] - m0n);
            s[j][2] = __expf(s[j][2] - m1n);
            s[j][3] = __expf(s[j][3] - m1n);
            sum0 += s[j][0] + s[j][1];
            sum1 += s[j][2] + s[j][3];
        }
        sum0 += __shfl_xor_sync(0xffffffffu, sum0, 1);
        sum0 += __shfl_xor_sync(0xffffffffu, sum0, 2);
        sum1 += __shfl_xor_sync(0xffffffffu, sum1, 1);
        sum1 += __shfl_xor_sync(0xffffffffu, sum1, 2);

        l0 = l0 * f0 + sum0;  m0 = m0n;
        l1 = l1 * f1 + sum1;  m1 = m1n;

        // Store P (tf32) to warp-private smem in A-frag-friendly layout
        #pragma unroll
        for (int j = 0; j < 8; ++j) {
            const int c = 8*j + 2*gk;
            *(float2*)&Pw[gr*PST     + c] = make_float2(f32_to_tf32(s[j][0]), f32_to_tf32(s[j][1]));
            *(float2*)&Pw[(gr+8)*PST + c] = make_float2(f32_to_tf32(s[j][2]), f32_to_tf32(s[j][3]));
        }

        // Rescale O
        #pragma unroll
        for (int j = 0; j < 16; ++j) {
            o[j][0] *= f0; o[j][1] *= f0;
            o[j][2] *= f1; o[j][3] *= f1;
        }
        __syncwarp();

        // O += P @ V
        #pragma unroll
        for (int t = 0; t < 8; ++t) {
            const int k0 = t * 8;
            const uint32_t a0 = __float_as_uint(Pw[gr*PST      + k0 + gk]);
            const uint32_t a1 = __float_as_uint(Pw[(gr+8)*PST  + k0 + gk]);
            const uint32_t a2 = __float_as_uint(Pw[gr*PST      + k0 + gk + 4]);
            const uint32_t a3 = __float_as_uint(Pw[(gr+8)*PST  + k0 + gk + 4]);
            const float* vr0 = &Vs[(k0 + gk)*KST     + gr];
            const float* vr1 = &Vs[(k0 + gk + 4)*KST + gr];
            #pragma unroll
            for (int j = 0; j < 16; ++j) {
                mma_tf32_16x8x8(o[j], a0, a1, a2, a3,
                                __float_as_uint(vr0[8*j]),
                                __float_as_uint(vr1[8*j]));
            }
        }
    }

    // Epilogue: normalize, round to tf32 (feeds pre-rounded O-gemm), store
    const float inv0 = 1.f / l0;
    const float inv1 = 1.f / l1;
    const int r0 = wrow + gr, r1 = r0 + 8;
    #pragma unroll
    for (int j = 0; j < 16; ++j) {
        const int col = head*HD + 8*j + 2*gk;
        *(float2*)&o_g[(size_t)r0*HID + col] =
            make_float2(f32_to_tf32(o[j][0]*inv0), f32_to_tf32(o[j][1]*inv0));
        *(float2*)&o_g[(size_t)r1*HID + col] =
            make_float2(f32_to_tf32(o[j][2]*inv1), f32_to_tf32(o[j][3]*inv1));
    }
}

// ---------------------------------------------------------------------------
extern "C" void kernel_launch(void* const* d_in, const int* in_sizes, int n_in,
                              void* d_out, int out_size)
{
    const float* x    = (const float*)d_in[0];
    const float* cosb = (const float*)d_in[1];
    const float* sinb = (const float*)d_in[2];
    const float* wq   = (const float*)d_in[3];
    const float* wk   = (const float*)d_in[4];
    const float* wv   = (const float*)d_in[5];
    const float* wo   = (const float*)d_in[6];
    float* out = (float*)d_out;

    float *q, *k, *v, *o, *xr, *wqkv, *wor;
    cudaGetSymbolAddress((void**)&q,    g_q);
    cudaGetSymbolAddress((void**)&k,    g_k);
    cudaGetSymbolAddress((void**)&v,    g_v);
    cudaGetSymbolAddress((void**)&o,    g_o);
    cudaGetSymbolAddress((void**)&xr,   g_xr);
    cudaGetSymbolAddress((void**)&wqkv, g_wqkv);
    cudaGetSymbolAddress((void**)&wor,  g_wor);

    cudaFuncSetAttribute(gemm_qkv,
                         cudaFuncAttributeMaxDynamicSharedMemorySize, GEMM_SMEM);
    cudaFuncSetAttribute(gemm_o,
                         cudaFuncAttributeMaxDynamicSharedMemorySize, GEMM_SMEM);
    cudaFuncSetAttribute(flash_mma,
                         cudaFuncAttributeMaxDynamicSharedMemorySize, FL_SMEM);

    // Pre-round all inputs to tf32 in ONE launch
    roundcvt_all<<<1184, 256>>>((const float4*)x, (const float4*)wq,
                                (const float4*)wk, (const float4*)wv,
                                (const float4*)wo,
                                (float4*)xr, (float4*)wqkv, (float4*)wor);

    // Fused QKV projection (persistent CTAs: 296 slots over 384 tiles)
    gemm_qkv<<<296, 256, GEMM_SMEM>>>(xr, wqkv, q, k, v);

    // RoPE on q, k
    rope_kernel<<<(SEQ*NH *32)/256, 256>>>(q, cosb, sinb, NH);
    rope_kernel<<<(SEQ*NKV*32)/256, 256>>>(k, cosb, sinb, NKV);

    // Causal GQA flash attention (BM=128, 8 warps, Q in regs)
    flash_mma<<<dim3(SEQ/128, NH), 256, FL_SMEM>>>(q, k, v, o);

    // Output projection
    gemm_o<<<dim3(HID/128, SEQ/128), 256, GEMM_SMEM>>>(o, wor, out);
}

// round 17
// speedup vs baseline: 1.0474x; 1.0474x over previous
#include <cuda_runtime.h>
#include <cstdint>
#include <math.h>

#define SEQ 2048
#define HID 2048
#define NH  16
#define NKV 4
#define HD  128
#define KVD (NKV*HD)   // 512
#define NQKV (HID + 2*KVD)   // 3072

// Scratch (no cudaMalloc allowed)
__device__ float g_q[SEQ*HID];
__device__ float g_k[SEQ*KVD];
__device__ float g_v[SEQ*KVD];
__device__ float g_o[SEQ*HID];
__device__ float g_xr[SEQ*HID];        // tf32-rounded x
__device__ float g_wqkv[NQKV*HID];     // tf32-rounded [wq;wk;wv]
__device__ float g_wor[HID*HID];       // tf32-rounded wo

// fp32 -> tf32 round-to-nearest
__device__ __forceinline__ float f32_to_tf32(float x) {
    uint32_t y;
    asm("cvt.rna.tf32.f32 %0, %1;" : "=r"(y) : "f"(x));
    return __uint_as_float(y);
}

__device__ __forceinline__ void mma_tf32_16x8x8(
    float c[4], uint32_t a0, uint32_t a1, uint32_t a2, uint32_t a3,
    uint32_t b0, uint32_t b1)
{
    asm volatile(
        "mma.sync.aligned.m16n8k8.row.col.f32.tf32.tf32.f32 "
        "{%0,%1,%2,%3}, {%4,%5,%6,%7}, {%8,%9}, {%0,%1,%2,%3};"
        : "+f"(c[0]), "+f"(c[1]), "+f"(c[2]), "+f"(c[3])
        : "r"(a0), "r"(a1), "r"(a2), "r"(a3), "r"(b0), "r"(b1));
}

__device__ __forceinline__ void ldsm4(
    uint32_t& d0, uint32_t& d1, uint32_t& d2, uint32_t& d3, uint32_t addr)
{
    asm volatile("ldmatrix.sync.aligned.m8n8.x4.shared.b16 {%0,%1,%2,%3}, [%4];"
                 : "=r"(d0), "=r"(d1), "=r"(d2), "=r"(d3) : "r"(addr));
}

__device__ __forceinline__ uint32_t smem_to_u32(const void* p) {
    uint32_t a;
    asm("{ .reg .u64 t; cvta.to.shared.u64 t, %1; cvt.u32.u64 %0, t; }"
        : "=r"(a) : "l"(p));
    return a;
}

__device__ __forceinline__ void cp16(uint32_t dst, const void* src) {
    asm volatile("cp.async.cg.shared.global [%0], [%1], 16;" :: "r"(dst), "l"(src));
}
#define CP_COMMIT() asm volatile("cp.async.commit_group;")
#define CP_WAIT1()  asm volatile("cp.async.wait_group 1;")
#define CP_WAIT0()  asm volatile("cp.async.wait_group 0;")

// ============================================================================
// tf32 mma.sync GEMM mainloop (2-stage cp.async, ldmatrix frag loads)
// CTA 128x128, BK=32, 256 threads, warp grid 4m x 2n (warp tile 32x64)
// ============================================================================
#define BK 32
#define AST 36
#define ABUF (128*AST)
#define GEMM_SMEM (2*2*ABUF*4)           // 73728 bytes

__device__ __forceinline__ void gemm_mainloop(
    const float* __restrict__ A, const float* __restrict__ B,
    int row0, int col0, float* sm, float c[2][8][4])
{
    const int tid  = threadIdx.x;
    const int lane = tid & 31;
    const int wid  = tid >> 5;
    const int wm0  = (wid & 3) * 32;
    const int wn0  = (wid >> 2) * 64;
    const int lr   = tid >> 3;
    const int lc   = (tid & 7) * 4;

    const uint32_t smb = smem_to_u32(sm);

    const int mi = lane >> 3, r8 = lane & 7;
    const uint32_t a_off0 = (uint32_t)((wm0 +      (mi & 1)*8 + r8)*AST + (mi >> 1)*4) * 4;
    const uint32_t a_off1 = a_off0 + 16u*AST*4;
    uint32_t b_off[4];
    #pragma unroll
    for (int jp = 0; jp < 4; ++jp)
        b_off[jp] = (uint32_t)((wn0 + 16*jp + (mi >> 1)*8 + r8)*AST + (mi & 1)*4) * 4
                    + (uint32_t)ABUF*4;

    #pragma unroll
    for (int i = 0; i < 2; ++i)
        #pragma unroll
        for (int j = 0; j < 8; ++j)
            #pragma unroll
            for (int t = 0; t < 4; ++t) c[i][j][t] = 0.f;

    // prologue: stage kb=0 into buf 0
    #pragma unroll
    for (int it = 0; it < 4; ++it) {
        const int r = lr + it * 32;
        cp16(smb + (uint32_t)(r*AST + lc)*4,          A + (size_t)(row0 + r)*HID + lc);
        cp16(smb + (uint32_t)(ABUF + r*AST + lc)*4,   B + (size_t)(col0 + r)*HID + lc);
    }
    CP_COMMIT();

    const int NKB = HID / BK;   // 64
    for (int kb = 0; kb < NKB; ++kb) {
        const int cur = kb & 1;
        if (kb + 1 < NKB) {
            const int nxt = 1 - cur;
            const int k0g = (kb + 1) * BK;
            #pragma unroll
            for (int it = 0; it < 4; ++it) {
                const int r = lr + it * 32;
                cp16(smb + (uint32_t)(nxt*2*ABUF + r*AST + lc)*4,
                     A + (size_t)(row0 + r)*HID + k0g + lc);
                cp16(smb + (uint32_t)(nxt*2*ABUF + ABUF + r*AST + lc)*4,
                     B + (size_t)(col0 + r)*HID + k0g + lc);
            }
            CP_COMMIT();
            CP_WAIT1();
        } else {
            CP_WAIT0();
        }
        __syncthreads();

        const uint32_t bufb = smb + (uint32_t)(cur * 2 * ABUF) * 4;
        #pragma unroll
        for (int s = 0; s < 4; ++s) {
            const uint32_t soff = (uint32_t)s * 32;
            uint32_t af[2][4], bf[8][2];
            ldsm4(af[0][0], af[0][1], af[0][2], af[0][3], bufb + a_off0 + soff);
            ldsm4(af[1][0], af[1][1], af[1][2], af[1][3], bufb + a_off1 + soff);
            #pragma unroll
            for (int jp = 0; jp < 4; ++jp)
                ldsm4(bf[2*jp][0], bf[2*jp][1], bf[2*jp+1][0], bf[2*jp+1][1],
                      bufb + b_off[jp] + soff);
            #pragma unroll
            for (int i = 0; i < 2; ++i)
                #pragma unroll
                for (int j = 0; j < 8; ++j)
                    mma_tf32_16x8x8(c[i][j], af[i][0], af[i][1], af[i][2], af[i][3],
                                    bf[j][0], bf[j][1]);
        }
        __syncthreads();
    }
}

// Persistent fused QKV projection: C[2048, 3072] = xr @ Wqkv^T, routed.
#define QKV_TX (NQKV/128)      // 24
#define QKV_NT (QKV_TX * (SEQ/128))   // 384 tiles
__global__ __launch_bounds__(256, 2) void gemm_qkv(
    const float* __restrict__ A, const float* __restrict__ B,
    float* __restrict__ Cq, float* __restrict__ Ck, float* __restrict__ Cv)
{
    extern __shared__ float sm[];
    const int lane = threadIdx.x & 31;
    const int wid  = threadIdx.x >> 5;
    const int wm0  = (wid & 3) * 32;
    const int wn0  = (wid >> 2) * 64;
    const int gr   = lane >> 2;
    const int gk   = lane & 3;

    for (int tidx = blockIdx.x; tidx < QKV_NT; tidx += gridDim.x) {
        const int row0 = (tidx / QKV_TX) * 128;
        const int col0 = (tidx % QKV_TX) * 128;

        float c[2][8][4];
        gemm_mainloop(A, B, row0, col0, sm, c);

        float* Cd; int ldc, cb;
        if (col0 < HID)            { Cd = Cq; ldc = HID; cb = col0; }
        else if (col0 < HID + KVD) { Cd = Ck; ldc = KVD; cb = col0 - HID; }
        else                       { Cd = Cv; ldc = KVD; cb = col0 - HID - KVD; }

        #pragma unroll
        for (int i = 0; i < 2; ++i) {
            #pragma unroll
            for (int j = 0; j < 8; ++j) {
                const int colb = cb + wn0 + j*8 + gk*2;
                const int rowa = row0 + wm0 + i*16 + gr;
                *(float2*)&Cd[(size_t)rowa * ldc + colb]       = make_float2(c[i][j][0], c[i][j][1]);
                *(float2*)&Cd[(size_t)(rowa + 8) * ldc + colb] = make_float2(c[i][j][2], c[i][j][3]);
            }
        }
    }
}

// Plain GEMM (O projection): C[2048, 2048] = A @ B^T (256 tiles, 1 wave)
__global__ __launch_bounds__(256, 2) void gemm_o(
    const float* __restrict__ A, const float* __restrict__ B,
    float* __restrict__ C)
{
    extern __shared__ float sm[];
    const int row0 = blockIdx.y * 128;
    const int col0 = blockIdx.x * 128;

    float c[2][8][4];
    gemm_mainloop(A, B, row0, col0, sm, c);

    const int lane = threadIdx.x & 31;
    const int wid  = threadIdx.x >> 5;
    const int wm0  = (wid & 3) * 32;
    const int wn0  = (wid >> 2) * 64;
    const int gr   = lane >> 2;
    const int gk   = lane & 3;

    #pragma unroll
    for (int i = 0; i < 2; ++i) {
        #pragma unroll
        for (int j = 0; j < 8; ++j) {
            const int colb = col0 + wn0 + j*8 + gk*2;
            const int rowa = row0 + wm0 + i*16 + gr;
            *(float2*)&C[(size_t)rowa * HID + colb]       = make_float2(c[i][j][0], c[i][j][1]);
            *(float2*)&C[(size_t)(rowa + 8) * HID + colb] = make_float2(c[i][j][2], c[i][j][3]);
        }
    }
}

// ---------------------------------------------------------------------------
// Fused elementwise tf32 rounding: x, wq|wk|wv -> wqkv, wo  (one launch)
// ---------------------------------------------------------------------------
#define N4_X   (SEQ*HID/4)
#define N4_WQ  (HID*HID/4)
#define N4_WK  (KVD*HID/4)
#define N4_WV  (KVD*HID/4)
#define N4_WO  (HID*HID/4)
#define N4_TOT (N4_X + N4_WQ + N4_WK + N4_WV + N4_WO)

__global__ void roundcvt_all(
    const float4* __restrict__ x,  const float4* __restrict__ wq,
    const float4* __restrict__ wk, const float4* __restrict__ wv,
    const float4* __restrict__ wo,
    float4* __restrict__ xr, float4* __restrict__ wqkv, float4* __restrict__ wor)
{
    for (int i = blockIdx.x * blockDim.x + threadIdx.x; i < N4_TOT;
         i += gridDim.x * blockDim.x) {
        const float4* s; float4* d; int off = i;
        if (off < N4_X)                    { s = x;  d = xr; }
        else if ((off -= N4_X)  < N4_WQ)   { s = wq; d = wqkv; }
        else if ((off -= N4_WQ) < N4_WK)   { s = wk; d = wqkv + N4_WQ; }
        else if ((off -= N4_WK) < N4_WV)   { s = wv; d = wqkv + N4_WQ + N4_WK; }
        else                               { off -= N4_WV; s = wo; d = wor; }
        float4 v = s[off];
        d[off] = make_float4(f32_to_tf32(v.x), f32_to_tf32(v.y),
                             f32_to_tf32(v.z), f32_to_tf32(v.w));
    }
}

// ---------------------------------------------------------------------------
// Fused RoPE (q then k in one launch), in place. Same per-element math as
// the two-launch version; index ranges are disjoint.
// ---------------------------------------------------------------------------
#define ROPE_NQ (SEQ*NH*32)
#define ROPE_NK (SEQ*NKV*32)
#define ROPE_TOT (ROPE_NQ + ROPE_NK)

__global__ void rope_fused(float* __restrict__ qd, float* __restrict__ kd,
                           const float* __restrict__ cosv,
                           const float* __restrict__ sinv)
{
    int idx = blockIdx.x * blockDim.x + threadIdx.x;
    if (idx >= ROPE_TOT) return;

    float* data; int nheads;
    if (idx < ROPE_NQ) { data = qd; nheads = NH; }
    else               { idx -= ROPE_NQ; data = kd; nheads = NKV; }

    int i   = idx & 31;
    int rem = idx >> 5;
    int h   = rem % nheads;
    int s   = rem / nheads;

    float* p = data + ((size_t)s * nheads + h) * HD;
    int j0 = 2*i, j1 = 2*i + 1;

    float x0  = p[j0],     x1  = p[j1];
    float xp0 = p[64+j0],  xp1 = p[64+j1];
    float c0 = cosv[s*HD + j0], s0 = sinv[s*HD + j0];
    float c1 = cosv[s*HD + j1], s1 = sinv[s*HD + j1];

    float r0 = -x1;
    float r1 =  x0;

    p[j0]     =  r0*c0 + xp0*s0;
    p[j1]     =  r1*c1 + xp1*s1;
    p[64+j0]  = -r0*s0 + xp0*c0;
    p[64+j1]  = -r1*s1 + xp1*c1;
}

// ============================================================================
// Tensor-core causal flash attention (tf32 mma.sync), GQA.
// BM=64 (4 warps x m16), BN=64, HD=128. Q frags in registers; 2 CTAs/SM.
// ============================================================================
#define KST 132
#define PST 68
#define FL_KV   (64*KST)
#define FL_PBUF (16*PST)
#define FL_SMEM ((2*FL_KV + 4*FL_PBUF) * 4)       // 84992 bytes

__global__ __launch_bounds__(128, 2) void flash_mma(
    const float* __restrict__ q_g, const float* __restrict__ k_g,
    const float* __restrict__ v_g, float* __restrict__ o_g)
{
    extern __shared__ float sm[];
    float* Ks = sm;
    float* Vs = sm + FL_KV;

    const int tid  = threadIdx.x;
    const int lane = tid & 31;
    const int wid  = tid >> 5;
    const int gr   = lane >> 2;
    const int gk   = lane & 3;

    float* Pw = sm + 2*FL_KV + wid * FL_PBUF;

    const int qb    = gridDim.x - 1 - blockIdx.x;
    const int head  = blockIdx.y;
    const int kvh   = head >> 2;
    const int qrow0 = qb * 64;
    const int wrow  = qrow0 + wid * 16;
    const float scale = 0.08838834764831845f;

    // Q a-fragments in registers (loop-invariant across jb).
    uint32_t qa[16][4];
    {
        const float* qr0 = q_g + (size_t)(wrow + gr)     * HID + head*HD;
        const float* qr1 = q_g + (size_t)(wrow + gr + 8) * HID + head*HD;
        #pragma unroll
        for (int t = 0; t < 16; ++t) {
            const int k0 = t * 8;
            qa[t][0] = __float_as_uint(f32_to_tf32(qr0[k0 + gk]     * scale));
            qa[t][1] = __float_as_uint(f32_to_tf32(qr1[k0 + gk]     * scale));
            qa[t][2] = __float_as_uint(f32_to_tf32(qr0[k0 + gk + 4] * scale));
            qa[t][3] = __float_as_uint(f32_to_tf32(qr1[k0 + gk + 4] * scale));
        }
    }

    float o[16][4];
    #pragma unroll
    for (int j = 0; j < 16; ++j)
        #pragma unroll
        for (int t = 0; t < 4; ++t) o[j][t] = 0.f;
    float m0 = -1e30f, m1 = -1e30f, l0 = 0.f, l1 = 0.f;

    for (int jb = 0; jb <= qb; ++jb) {
        const int kr0 = jb * 64;
        __syncthreads();
        #pragma unroll
        for (int it = 0; it < 16; ++it) {
            const int r = wid + 4*it;
            float4 kv = *(const float4*)(k_g + (size_t)(kr0 + r)*KVD + kvh*HD + 4*lane);
            float4 kt = make_float4(f32_to_tf32(kv.x), f32_to_tf32(kv.y),
                                    f32_to_tf32(kv.z), f32_to_tf32(kv.w));
            *(float4*)&Ks[r*KST + 4*lane] = kt;
            float4 vv = *(const float4*)(v_g + (size_t)(kr0 + r)*KVD + kvh*HD + 4*lane);
            float4 vt = make_float4(f32_to_tf32(vv.x), f32_to_tf32(vv.y),
                                    f32_to_tf32(vv.z), f32_to_tf32(vv.w));
            *(float4*)&Vs[r*KST + 4*lane] = vt;
        }
        __syncthreads();

        // S = Q K^T
        float s[8][4];
        #pragma unroll
        for (int j = 0; j < 8; ++j)
            #pragma unroll
            for (int t = 0; t < 4; ++t) s[j][t] = 0.f;

        #pragma unroll
        for (int t = 0; t < 16; ++t) {
            const int k0 = t * 8;
            #pragma unroll
            for (int j = 0; j < 8; ++j) {
                const int base = (8*j + gr)*KST + k0 + gk;
                mma_tf32_16x8x8(s[j], qa[t][0], qa[t][1], qa[t][2], qa[t][3],
                                __float_as_uint(Ks[base]),
                                __float_as_uint(Ks[base + 4]));
            }
        }

        // Causal mask (diagonal tile only)
        if (jb == qb) {
            const int r0 = wrow + gr, r1 = r0 + 8;
            #pragma unroll
            for (int j = 0; j < 8; ++j) {
                const int col = kr0 + 8*j + 2*gk;
                if (col     > r0) s[j][0] = -1e30f;
                if (col + 1 > r0) s[j][1] = -1e30f;
                if (col     > r1) s[j][2] = -1e30f;
                if (col + 1 > r1) s[j][3] = -1e30f;
            }
        }

        // Online softmax
        float rmax0 = -1e30f, rmax1 = -1e30f;
        #pragma unroll
        for (int j = 0; j < 8; ++j) {
            rmax0 = fmaxf(rmax0, fmaxf(s[j][0], s[j][1]));
            rmax1 = fmaxf(rmax1, fmaxf(s[j][2], s[j][3]));
        }
        rmax0 = fmaxf(rmax0, __shfl_xor_sync(0xffffffffu, rmax0, 1));
        rmax0 = fmaxf(rmax0, __shfl_xor_sync(0xffffffffu, rmax0, 2));
        rmax1 = fmaxf(rmax1, __shfl_xor_sync(0xffffffffu, rmax1, 1));
        rmax1 = fmaxf(rmax1, __shfl_xor_sync(0xffffffffu, rmax1, 2));

        const float m0n = fmaxf(m0, rmax0);
        const float m1n = fmaxf(m1, rmax1);
        const float f0  = __expf(m0 - m0n);
        const float f1  = __expf(m1 - m1n);

        float sum0 = 0.f, sum1 = 0.f;
        #pragma unroll
        for (int j = 0; j < 8; ++j) {
            s[j][0] = __expf(s[j][0] - m0n);
            s[j][1] = __expf(s[j][1] - m0n);
            s[j][2] = __expf(s[j][2] - m1n);
            s[j][3] = __expf(s[j][3] - m1n);
            sum0 += s[j][0] + s[j][1];
            sum1 += s[j][2] + s[j][3];
        }
        sum0 += __shfl_xor_sync(0xffffffffu, sum0, 1);
        sum0 += __shfl_xor_sync(0xffffffffu, sum0, 2);
        sum1 += __shfl_xor_sync(0xffffffffu, sum1, 1);
        sum1 += __shfl_xor_sync(0xffffffffu, sum1, 2);

        l0 = l0 * f0 + sum0;  m0 = m0n;
        l1 = l1 * f1 + sum1;  m1 = m1n;

        // Store P (tf32) to warp-private smem in A-frag-friendly layout
        #pragma unroll
        for (int j = 0; j < 8; ++j) {
            const int c = 8*j + 2*gk;
            *(float2*)&Pw[gr*PST     + c] = make_float2(f32_to_tf32(s[j][0]), f32_to_tf32(s[j][1]));
            *(float2*)&Pw[(gr+8)*PST + c] = make_float2(f32_to_tf32(s[j][2]), f32_to_tf32(s[j][3]));
        }

        // Rescale O
        #pragma unroll
        for (int j = 0; j < 16; ++j) {
            o[j][0] *= f0; o[j][1] *= f0;
            o[j][2] *= f1; o[j][3] *= f1;
        }
        __syncwarp();

        // O += P @ V
        #pragma unroll
        for (int t = 0; t < 8; ++t) {
            const int k0 = t * 8;
            const uint32_t a0 = __float_as_uint(Pw[gr*PST      + k0 + gk]);
            const uint32_t a1 = __float_as_uint(Pw[(gr+8)*PST  + k0 + gk]);
            const uint32_t a2 = __float_as_uint(Pw[gr*PST      + k0 + gk + 4]);
            const uint32_t a3 = __float_as_uint(Pw[(gr+8)*PST  + k0 + gk + 4]);
            const float* vr0 = &Vs[(k0 + gk)*KST     + gr];
            const float* vr1 = &Vs[(k0 + gk + 4)*KST + gr];
            #pragma unroll
            for (int j = 0; j < 16; ++j) {
                mma_tf32_16x8x8(o[j], a0, a1, a2, a3,
                                __float_as_uint(vr0[8*j]),
                                __float_as_uint(vr1[8*j]));
            }
        }
    }

    // Epilogue: normalize, round to tf32 (feeds pre-rounded O-gemm), store
    const float inv0 = 1.f / l0;
    const float inv1 = 1.f / l1;
    const int r0 = wrow + gr, r1 = r0 + 8;
    #pragma unroll
    for (int j = 0; j < 16; ++j) {
        const int col = head*HD + 8*j + 2*gk;
        *(float2*)&o_g[(size_t)r0*HID + col] =
            make_float2(f32_to_tf32(o[j][0]*inv0), f32_to_tf32(o[j][1]*inv0));
        *(float2*)&o_g[(size_t)r1*HID + col] =
            make_float2(f32_to_tf32(o[j][2]*inv1), f32_to_tf32(o[j][3]*inv1));
    }
}

// ---------------------------------------------------------------------------
extern "C" void kernel_launch(void* const* d_in, const int* in_sizes, int n_in,
                              void* d_out, int out_size)
{
    const float* x    = (const float*)d_in[0];
    const float* cosb = (const float*)d_in[1];
    const float* sinb = (const float*)d_in[2];
    const float* wq   = (const float*)d_in[3];
    const float* wk   = (const float*)d_in[4];
    const float* wv   = (const float*)d_in[5];
    const float* wo   = (const float*)d_in[6];
    float* out = (float*)d_out;

    float *q, *k, *v, *o, *xr, *wqkv, *wor;
    cudaGetSymbolAddress((void**)&q,    g_q);
    cudaGetSymbolAddress((void**)&k,    g_k);
    cudaGetSymbolAddress((void**)&v,    g_v);
    cudaGetSymbolAddress((void**)&o,    g_o);
    cudaGetSymbolAddress((void**)&xr,   g_xr);
    cudaGetSymbolAddress((void**)&wqkv, g_wqkv);
    cudaGetSymbolAddress((void**)&wor,  g_wor);

    cudaFuncSetAttribute(gemm_qkv,
                         cudaFuncAttributeMaxDynamicSharedMemorySize, GEMM_SMEM);
    cudaFuncSetAttribute(gemm_o,
                         cudaFuncAttributeMaxDynamicSharedMemorySize, GEMM_SMEM);
    cudaFuncSetAttribute(flash_mma,
                         cudaFuncAttributeMaxDynamicSharedMemorySize, FL_SMEM);

    // Pre-round all inputs to tf32 in ONE launch
    roundcvt_all<<<1184, 256>>>((const float4*)x, (const float4*)wq,
                                (const float4*)wk, (const float4*)wv,
                                (const float4*)wo,
                                (float4*)xr, (float4*)wqkv, (float4*)wor);

    // Fused QKV projection (persistent CTAs: 296 slots over 384 tiles)
    gemm_qkv<<<296, 256, GEMM_SMEM>>>(xr, wqkv, q, k, v);

    // RoPE on q and k in ONE launch
    rope_fused<<<(ROPE_TOT + 255)/256, 256>>>(q, k, cosb, sinb);

    // Causal GQA flash attention (BM=64, Q in regs, 2 CTAs/SM)
    flash_mma<<<dim3(SEQ/64, NH), 128, FL_SMEM>>>(q, k, v, o);

    // Output projection
    gemm_o<<<dim3(HID/128, SEQ/128), 256, GEMM_SMEM>>>(o, wor, out);
}